// round 14
// baseline (speedup 1.0000x reference)
#include <cuda_runtime.h>
#include <cuda_fp16.h>
#include <cuda.h>
#include <cstdint>

// Shape: M=8192 (B=4,S=2048), K=4096, N=11008
// Harness dtypes: x f32, qweight i32, scales f32, qzeros i32, out f32.
#define MTOT 8192
#define KTOT 4096
#define NTOT 11008
#define K2TOT (KTOT / 2)

#define BM 128
#define BN 128
#define BK 128                       // two 64-col SW128 sub-tiles
#define STAGES 3
#define KTILES (KTOT / BK)           // 32
#define HKT (KTILES / 2)             // 16 (k-split point)
#define SUB_BYTES (128 * 128)
#define A_ST_BYTES (2 * SUB_BYTES)   // 32768
#define B_ST_BYTES (2 * SUB_BYTES)   // 32768

#define MT_TILES (MTOT / BM)         // 64
#define NT_TILES (NTOT / BN)         // 86
#define TOTAL_TILES (MT_TILES * NT_TILES)  // 5504
#define BAND 8
#define GRID_CTAS 148
#define NFULL (TOTAL_TILES / GRID_CTAS)    // 37
#define NREM (TOTAL_TILES % GRID_CTAS)     // 28

#define DQ_BX (NTOT / 64)            // 172 dequant units (64 n-cols) per k-chunk

// SMEM layout: TMA ring + dq transpose buffer for the aux warps
#define OFF_FULL 0
#define OFF_EMPTY (8 * STAGES)
#define OFF_A 1024
#define OFF_B (OFF_A + STAGES * A_ST_BYTES)
#define OFF_DQ (OFF_B + STAGES * B_ST_BYTES)        // 197632
#define SMEM_TOTAL (OFF_DQ + 64 * 136 * 2)          // 215040

// 8 consumer + 1 producer + 3 aux warps = 384 threads -> reg cap 170 (>=160
// needed by the consumer mainloop; 4 aux warps = 416 thr capped at 157 and
// spilled accumulators in round 13).
#define NTHREADS 384

// Scratch: Wt[N][K] f16 (90MB), xh f16 (64MB), k-split partials,
// g_sync[0..32) = per-k-chunk aux counters, g_sync[32..60) = k-split flags
__device__ __align__(1024) __half g_Wt[(size_t)NTOT * KTOT];
__device__ __align__(1024) __half g_xh[(size_t)MTOT * KTOT];
__device__ __align__(1024) float g_part[(size_t)NREM * BM * BN];
__device__ __align__(256) int g_sync[64];

// ---------------------------------------------------------------------------
// helpers
// ---------------------------------------------------------------------------
__device__ __forceinline__ uint32_t smem_u32(const void* p) {
    uint32_t a;
    asm("{ .reg .u64 t; cvta.to.shared.u64 t, %1; cvt.u32.u64 %0, t; }"
        : "=r"(a) : "l"(p));
    return a;
}

__device__ __forceinline__ void mbar_init(uint32_t mbar, uint32_t count) {
    asm volatile("mbarrier.init.shared.b64 [%0], %1;" :: "r"(mbar), "r"(count) : "memory");
}

__device__ __forceinline__ void mbar_expect_tx(uint32_t mbar, uint32_t bytes) {
    asm volatile("mbarrier.arrive.expect_tx.shared.b64 _, [%0], %1;"
                 :: "r"(mbar), "r"(bytes) : "memory");
}

__device__ __forceinline__ void mbar_arrive(uint32_t mbar) {
    asm volatile("mbarrier.arrive.shared.b64 _, [%0];" :: "r"(mbar) : "memory");
}

__device__ __forceinline__ void mbar_wait(uint32_t mbar, uint32_t parity) {
    asm volatile(
        "{\n\t"
        ".reg .pred P;\n\t"
        "WLOOP_%=:\n\t"
        "mbarrier.try_wait.parity.acquire.cta.shared::cta.b64 P, [%0], %1, 0x989680;\n\t"
        "@P bra.uni WDONE_%=;\n\t"
        "bra.uni WLOOP_%=;\n\t"
        "WDONE_%=:\n\t"
        "}"
        :: "r"(mbar), "r"(parity) : "memory");
}

__device__ __forceinline__ void mbar_wait_relaxed(uint32_t mbar, uint32_t parity) {
    asm volatile(
        "{\n\t"
        ".reg .pred P;\n\t"
        "WLOOP_%=:\n\t"
        "mbarrier.try_wait.parity.relaxed.cta.shared::cta.b64 P, [%0], %1, 0x989680;\n\t"
        "@P bra.uni WDONE_%=;\n\t"
        "bra.uni WLOOP_%=;\n\t"
        "WDONE_%=:\n\t"
        "}"
        :: "r"(mbar), "r"(parity) : "memory");
}

__device__ __forceinline__ void tma_load_2d(uint32_t smem_dst, const void* map,
                                            int cx, int cy, uint32_t mbar) {
    asm volatile(
        "cp.async.bulk.tensor.2d.shared::cta.global.tile.mbarrier::complete_tx::bytes "
        "[%0], [%1, {%2, %3}], [%4];"
        :: "r"(smem_dst), "l"(map), "r"(cx), "r"(cy), "r"(mbar) : "memory");
}

__device__ __forceinline__ void ldsm_x4(uint32_t& r0, uint32_t& r1, uint32_t& r2,
                                        uint32_t& r3, uint32_t addr) {
    asm volatile("ldmatrix.sync.aligned.m8n8.x4.shared.b16 {%0,%1,%2,%3}, [%4];"
                 : "=r"(r0), "=r"(r1), "=r"(r2), "=r"(r3) : "r"(addr));
}

__device__ __forceinline__ void mma16816(float* c, const uint32_t* a, const uint32_t* b) {
    asm volatile(
        "mma.sync.aligned.m16n8k16.row.col.f32.f16.f16.f32 "
        "{%0,%1,%2,%3}, {%4,%5,%6,%7}, {%8,%9}, {%0,%1,%2,%3};"
        : "+f"(c[0]), "+f"(c[1]), "+f"(c[2]), "+f"(c[3])
        : "r"(a[0]), "r"(a[1]), "r"(a[2]), "r"(a[3]), "r"(b[0]), "r"(b[1]));
}

// banded raster: 8 consecutive m-tiles sweep n together (L2 reuse)
__device__ __forceinline__ void tile_coords(int t, int& m0, int& n0) {
    const int band = t / (NT_TILES * BAND);
    const int r = t % (NT_TILES * BAND);
    m0 = (band * BAND + (r & (BAND - 1))) * BM;
    n0 = (r / BAND) * BN;
}

// Work list: items 0..NFULL-1 full tiles; item NFULL (bid<2*NREM) = K-half of
// a remainder tile (LAST: by then all k-chunks are dequantized).
__device__ __forceinline__ int num_work(int bid) {
    return NFULL + ((bid < 2 * NREM) ? 1 : 0);
}
__device__ __forceinline__ void work_item(int bid, int i, int& t, int& nkt,
                                          int& kbase, int& mode, int& slot) {
    if (i < NFULL) {
        t = bid + i * GRID_CTAS; nkt = KTILES; kbase = 0; mode = 0; slot = 0;
    } else if (bid < NREM) {
        t = NFULL * GRID_CTAS + bid; nkt = HKT; kbase = 0; mode = 1; slot = bid;
    } else {
        t = NFULL * GRID_CTAS + (bid - NREM); nkt = HKT; kbase = HKT; mode = 2;
        slot = bid - NREM;
    }
}

// ---------------------------------------------------------------------------
// ONE fused kernel: warps 0-7 = MMA consumers, warp 8 = TMA producer (gated on
// per-k-chunk aux counters), warps 9-11 = aux (x f32->f16 convert + int4
// dequant+transpose), processed k-chunk-major.
// ---------------------------------------------------------------------------
__global__ void __launch_bounds__(NTHREADS, 1) int4gemm_kernel(
    const __grid_constant__ CUtensorMap tma_a,
    const __grid_constant__ CUtensorMap tma_b,
    float* __restrict__ out,
    const float4* __restrict__ xin,
    const int* __restrict__ qw,
    const float* __restrict__ sc,
    const int* __restrict__ qz,
    __half* __restrict__ xh,
    __half* __restrict__ wt) {
    extern __shared__ __align__(1024) char smem[];
    const uint32_t sb = smem_u32(smem);
    const int tid = threadIdx.x;
    const int wid = tid >> 5;
    const int l = tid & 31;
    const int bid = blockIdx.x;
    const int nwork = num_work(bid);

    if (tid == 0) {
#pragma unroll
        for (int s = 0; s < STAGES; s++) {
            mbar_init(sb + OFF_FULL + 8 * s, 1);
            mbar_init(sb + OFF_EMPTY + 8 * s, 8);
        }
        asm volatile("fence.mbarrier_init.release.cluster;" ::: "memory");
    }
    __syncthreads();

    // ======================= AUX warps (wid 9-11, 96 threads) =============
    if (wid >= 9) {
        const int atid = tid - 9 * 32;      // 0..95
        const int lane = atid & 31;
        const int arow = atid >> 5;         // 0..2
        const int cr0 = (bid * MTOT) / GRID_CTAS;
        const int cr1 = ((bid + 1) * MTOT) / GRID_CTAS;
        __half* dqs = reinterpret_cast<__half*>(smem + OFF_DQ);  // [64][136]

        for (int kt = 0; kt < 32; kt++) {
            // ---- convert x[:, kt*128 .. +128) rows [cr0, cr1), 3-warp stripe
            for (int r = cr0 + arow; r < cr1; r += 3) {
                const float4 v = __ldcs(&xin[(size_t)r * (KTOT / 4) + kt * 32 + lane]);
                __half2 lo = __floats2half2_rn(v.x, v.y);
                __half2 hi = __floats2half2_rn(v.z, v.w);
                uint2 pk;
                pk.x = *reinterpret_cast<const uint32_t*>(&lo);
                pk.y = *reinterpret_cast<const uint32_t*>(&hi);
                *reinterpret_cast<uint2*>(&xh[(size_t)r * KTOT + kt * 128 + lane * 4]) = pk;
            }
            // ---- dequant units u (64 n-cols x 128 k) for this k-chunk ----
            for (int u = bid; u < DQ_BX; u += GRID_CTAS) {
                const int n0 = u * 64;
                const int k20 = kt * 64;
                if (atid < 64) {  // 64 low threads own one n-col each
                    const int n = n0 + atid;
                    const float sf = sc[(size_t)kt * NTOT + n];
                    const int zq = qz[(size_t)(kt >> 1) * NTOT + n];
                    const int z = (zq >> ((kt & 1) * 4)) & 15;
#pragma unroll 8
                    for (int k2r = 0; k2r < 64; k2r++) {
                        const int q = __ldcs(&qw[(size_t)(k20 + k2r) * NTOT + n]);
                        dqs[atid * 136 + 2 * k2r] =
                            __float2half_rn((float)((q & 15) - z) * sf);
                        dqs[atid * 136 + 2 * k2r + 1] =
                            __float2half_rn((float)(((q >> 4) & 15) - z) * sf);
                    }
                }
                asm volatile("bar.sync 2, 96;" ::: "memory");
                // transpose out: 1024 uint4 chunks striped over 96 threads
                for (int idx = atid; idx < 1024; idx += 96) {
                    const int rn = idx >> 4;
                    const int cc = idx & 15;
                    uint4 v = *reinterpret_cast<const uint4*>(&dqs[rn * 136 + cc * 8]);
                    *reinterpret_cast<uint4*>(
                        &wt[(size_t)(n0 + rn) * KTOT + 2 * k20 + cc * 8]) = v;
                }
                asm volatile("bar.sync 2, 96;" ::: "memory");
            }
            // ---- publish chunk completion (release) ----
            __threadfence();
            asm volatile("bar.sync 2, 96;" ::: "memory");
            if (atid == 0) atomicAdd(&g_sync[kt], 1);
        }
        return;
    }

    // ======================= PRODUCER warp (wid 8) ========================
    if (wid == 8) {
        if (l == 0) {
            int s = 0, pe = 1, kready = 0;
            for (int i = 0; i < nwork; i++) {
                int t, nkt, kbase, mode, slot;
                work_item(bid, i, t, nkt, kbase, mode, slot);
                int m0, n0;
                tile_coords(t, m0, n0);
                for (int kt = 0; kt < nkt; kt++) {
                    const int ch = kbase + kt;
                    if (ch >= kready) {
                        while (kready <= ch) {
                            if (__ldcg(&g_sync[kready]) == GRID_CTAS) kready++;
                        }
                        __threadfence();
                    }
                    const int kc = ch * BK;
                    mbar_wait_relaxed(sb + OFF_EMPTY + 8 * s, pe);
                    const uint32_t fb = sb + OFF_FULL + 8 * s;
                    mbar_expect_tx(fb, A_ST_BYTES + B_ST_BYTES);
                    const uint32_t aD = sb + OFF_A + s * A_ST_BYTES;
                    const uint32_t bD = sb + OFF_B + s * B_ST_BYTES;
                    tma_load_2d(aD, (const void*)&tma_a, kc, m0, fb);
                    tma_load_2d(aD + SUB_BYTES, (const void*)&tma_a, kc + 64, m0, fb);
                    tma_load_2d(bD, (const void*)&tma_b, kc, n0, fb);
                    tma_load_2d(bD + SUB_BYTES, (const void*)&tma_b, kc + 64, n0, fb);
                    if (++s == STAGES) { s = 0; pe ^= 1; }
                }
            }
        }
        return;
    }

    // ======================= CONSUMERS (wid 0-7) ==========================
    const int wm = wid & 3;
    const int wn = wid >> 2;

    const uint32_t rowA = wm * 32 + (l & 15);
    const uint32_t xorA = (rowA & 7) << 4;
    const uint32_t colA = (l >> 4) * 16;
    const uint32_t aOff = rowA * 128;

    const uint32_t rowB = wn * 64 + (l & 7) + ((l >> 4) & 1) * 8;
    const uint32_t xorB = (l & 7) << 4;
    const uint32_t colB = ((l >> 3) & 1) * 16;
    const uint32_t bOff = rowB * 128;

    float c[2][8][4];
    uint32_t a[2][2][4];
    uint32_t b[2][8][2];

#define LOADF(buf, ksub)                                                        \
    do {                                                                        \
        const uint32_t aS = aB + ((ksub) >> 2) * SUB_BYTES;                     \
        const uint32_t bS = bB + ((ksub) >> 2) * SUB_BYTES;                     \
        const uint32_t kc = ((ksub) & 3) * 32;                                  \
        _Pragma("unroll")                                                       \
        for (int mt = 0; mt < 2; mt++)                                          \
            ldsm_x4(a[buf][mt][0], a[buf][mt][1], a[buf][mt][2], a[buf][mt][3], \
                    aS + aOff + mt * 2048 + ((kc + colA) ^ xorA));              \
        _Pragma("unroll")                                                       \
        for (int np = 0; np < 4; np++) {                                        \
            uint32_t r0, r1, r2, r3;                                            \
            ldsm_x4(r0, r1, r2, r3,                                             \
                    bS + bOff + np * 2048 + ((kc + colB) ^ xorB));              \
            b[buf][2 * np][0] = r0; b[buf][2 * np][1] = r1;                     \
            b[buf][2 * np + 1][0] = r2; b[buf][2 * np + 1][1] = r3;             \
        }                                                                       \
    } while (0)

#define MMABLK(buf)                                                             \
    do {                                                                        \
        _Pragma("unroll")                                                       \
        for (int mt = 0; mt < 2; mt++)                                          \
            _Pragma("unroll")                                                   \
            for (int nt = 0; nt < 8; nt++)                                      \
                mma16816(c[mt][nt], a[buf][mt], b[buf][nt]);                    \
    } while (0)

    int s = 0, pf = 0;
    const int rq = l >> 2;
    const int cq = (l & 3) * 2;

    for (int i = 0; i < nwork; i++) {
        int t, nkt, kbase, mode, slot;
        work_item(bid, i, t, nkt, kbase, mode, slot);
        int m0, n0;
        tile_coords(t, m0, n0);

#pragma unroll
        for (int mt = 0; mt < 2; mt++)
#pragma unroll
            for (int nt = 0; nt < 8; nt++)
#pragma unroll
                for (int j = 0; j < 4; j++) c[mt][nt][j] = 0.0f;

        mbar_wait(sb + OFF_FULL + 8 * s, pf);
        uint32_t aB = sb + OFF_A + s * A_ST_BYTES;
        uint32_t bB = sb + OFF_B + s * B_ST_BYTES;
        LOADF(0, 0);

        for (int kt = 0; kt < nkt; kt++) {
#pragma unroll
            for (int ks = 0; ks < 7; ks++) {
                LOADF((ks & 1) ^ 1, ks + 1);
                MMABLK(ks & 1);
            }
            MMABLK(1);
            if (l == 0) mbar_arrive(sb + OFF_EMPTY + 8 * s);
            if (++s == STAGES) { s = 0; pf ^= 1; }
            if (kt != nkt - 1) {
                mbar_wait(sb + OFF_FULL + 8 * s, pf);
                aB = sb + OFF_A + s * A_ST_BYTES;
                bB = sb + OFF_B + s * B_ST_BYTES;
                LOADF(0, 0);
            }
        }

        // ---- epilogue ----
        if (mode == 0) {
            const int mb = m0 + wm * 32;
            const int nb = n0 + wn * 64;
#pragma unroll
            for (int mt = 0; mt < 2; mt++) {
#pragma unroll
                for (int nt = 0; nt < 8; nt++) {
                    const size_t row = (size_t)(mb + mt * 16 + rq);
                    const size_t col = (size_t)(nb + nt * 8 + cq);
                    __stcs(reinterpret_cast<float2*>(&out[row * NTOT + col]),
                           make_float2(c[mt][nt][0], c[mt][nt][1]));
                    __stcs(reinterpret_cast<float2*>(&out[(row + 8) * NTOT + col]),
                           make_float2(c[mt][nt][2], c[mt][nt][3]));
                }
            }
        } else if (mode == 1) {
            float* scr = g_part + (size_t)slot * (BM * BN);
#pragma unroll
            for (int mt = 0; mt < 2; mt++) {
#pragma unroll
                for (int nt = 0; nt < 8; nt++) {
                    const int row = wm * 32 + mt * 16 + rq;
                    const int col = wn * 64 + nt * 8 + cq;
                    *reinterpret_cast<float2*>(&scr[row * BN + col]) =
                        make_float2(c[mt][nt][0], c[mt][nt][1]);
                    *reinterpret_cast<float2*>(&scr[(row + 8) * BN + col]) =
                        make_float2(c[mt][nt][2], c[mt][nt][3]);
                }
            }
            asm volatile("bar.sync 1, 256;" ::: "memory");
            if (tid == 0) {
                __threadfence();
                atomicExch(&g_sync[32 + slot], 1);
            }
        } else {
            if (tid == 0) {
                while (atomicAdd(&g_sync[32 + slot], 0) == 0) {}
                __threadfence();
            }
            asm volatile("bar.sync 1, 256;" ::: "memory");
            const float* scr = g_part + (size_t)slot * (BM * BN);
            const int mb = m0 + wm * 32;
            const int nb = n0 + wn * 64;
#pragma unroll
            for (int mt = 0; mt < 2; mt++) {
#pragma unroll
                for (int nt = 0; nt < 8; nt++) {
                    const int row = wm * 32 + mt * 16 + rq;
                    const int col = wn * 64 + nt * 8 + cq;
                    float2 p0 = *reinterpret_cast<const float2*>(&scr[row * BN + col]);
                    float2 p1 = *reinterpret_cast<const float2*>(&scr[(row + 8) * BN + col]);
                    const size_t grow = (size_t)(mb + mt * 16 + rq);
                    const size_t gcol = (size_t)(nb + nt * 8 + cq);
                    __stcs(reinterpret_cast<float2*>(&out[grow * NTOT + gcol]),
                           make_float2(c[mt][nt][0] + p0.x, c[mt][nt][1] + p0.y));
                    __stcs(reinterpret_cast<float2*>(&out[(grow + 8) * NTOT + gcol]),
                           make_float2(c[mt][nt][2] + p1.x, c[mt][nt][3] + p1.y));
                }
            }
        }
    }
#undef LOADF
#undef MMABLK
}

// ---------------------------------------------------------------------------
// host side
// ---------------------------------------------------------------------------
typedef CUresult (*PFN_encodeTiled)(
    CUtensorMap*, CUtensorMapDataType, cuuint32_t, void*,
    const cuuint64_t*, const cuuint64_t*, const cuuint32_t*, const cuuint32_t*,
    CUtensorMapInterleave, CUtensorMapSwizzle, CUtensorMapL2promotion,
    CUtensorMapFloatOOBfill);

static void encode_2d_f16(PFN_encodeTiled enc, CUtensorMap* m, void* ptr,
                          uint64_t d0, uint64_t d1, uint32_t b0, uint32_t b1) {
    cuuint64_t dims[2] = {d0, d1};
    cuuint64_t strides[1] = {d0 * 2};
    cuuint32_t box[2] = {b0, b1};
    cuuint32_t es[2] = {1, 1};
    enc(m, CU_TENSOR_MAP_DATA_TYPE_FLOAT16, 2, ptr, dims, strides, box, es,
        CU_TENSOR_MAP_INTERLEAVE_NONE, CU_TENSOR_MAP_SWIZZLE_128B,
        CU_TENSOR_MAP_L2_PROMOTION_L2_128B, CU_TENSOR_MAP_FLOAT_OOB_FILL_NONE);
}

extern "C" void kernel_launch(void* const* d_in, const int* in_sizes, int n_in,
                              void* d_out, int out_size) {
    const float* x = (const float*)d_in[0];
    const int* qw = (const int*)d_in[1];
    const float* sc = (const float*)d_in[2];
    const int* qz = (const int*)d_in[3];
    float* out = (float*)d_out;

    void* wt = nullptr;
    cudaGetSymbolAddress(&wt, g_Wt);
    void* xh = nullptr;
    cudaGetSymbolAddress(&xh, g_xh);
    void* syncp = nullptr;
    cudaGetSymbolAddress(&syncp, g_sync);

    // reset chunk counters + k-split flags (async, capturable)
    cudaMemsetAsync(syncp, 0, 64 * sizeof(int));

    PFN_encodeTiled enc = nullptr;
    cudaDriverEntryPointQueryResult qr;
    cudaGetDriverEntryPointByVersion("cuTensorMapEncodeTiled", (void**)&enc,
                                     12000, cudaEnableDefault, &qr);

    CUtensorMap map_a, map_b;
    encode_2d_f16(enc, &map_a, xh, KTOT, MTOT, 64, BM);   // xh[M,K] f16
    encode_2d_f16(enc, &map_b, wt, KTOT, NTOT, 64, BN);   // Wt[N,K] f16

    cudaFuncSetAttribute(int4gemm_kernel,
                         cudaFuncAttributeMaxDynamicSharedMemorySize, SMEM_TOTAL);

    int4gemm_kernel<<<GRID_CTAS, NTHREADS, SMEM_TOTAL>>>(
        map_a, map_b, out, (const float4*)x, qw, sc, qz, (__half*)xh, (__half*)wt);
}

// round 15
// speedup vs baseline: 1.4536x; 1.4536x over previous
#include <cuda_runtime.h>
#include <cuda_fp16.h>
#include <cuda.h>
#include <cstdint>

// Shape: M=8192 (B=4,S=2048), K=4096, N=11008
// Harness dtypes: x f32, qweight i32, scales f32, qzeros i32, out f32.
#define MTOT 8192
#define KTOT 4096
#define NTOT 11008
#define K2TOT (KTOT / 2)

#define BM 128
#define BN 128
#define BK 128                       // two 64-col SW128 sub-tiles
#define STAGES 3
#define KTILES (KTOT / BK)           // 32
#define HKT (KTILES / 2)             // 16 (k-split point)
#define SUB_BYTES (128 * 128)
#define A_ST_BYTES (2 * SUB_BYTES)   // 32768
#define B_ST_BYTES (2 * SUB_BYTES)   // 32768

#define MT_TILES (MTOT / BM)         // 64
#define NT_TILES (NTOT / BN)         // 86
#define TOTAL_TILES (MT_TILES * NT_TILES)  // 5504
#define BAND 8
#define GRID_CTAS 148
#define NFULL (TOTAL_TILES / GRID_CTAS)    // 37
#define NREM (TOTAL_TILES % GRID_CTAS)     // 28

// SMEM layout (occ 1)
#define OFF_FULL 0
#define OFF_EMPTY (8 * STAGES)
#define OFF_A 1024
#define OFF_B (OFF_A + STAGES * A_ST_BYTES)
#define SMEM_TOTAL (OFF_B + STAGES * B_ST_BYTES)   // 197632

// conv: 4 float4 per thread -> 8192 blocks; dequant: 172*32 = 5504 blocks
#define CONV_BLOCKS ((MTOT * KTOT) / (256 * 16))   // 8192
#define DQ_BX (NTOT / 64)                          // 172
#define DQ_BY (K2TOT / 64)                         // 32

// Scratch: Wt[N][K] f16 (90MB), xh f16 (64MB), k-split partials + flags
__device__ __align__(1024) __half g_Wt[(size_t)NTOT * KTOT];
__device__ __align__(1024) __half g_xh[(size_t)MTOT * KTOT];
__device__ __align__(1024) float g_part[(size_t)NREM * BM * BN];
__device__ int g_flag[NREM];

// ---------------------------------------------------------------------------
// helpers
// ---------------------------------------------------------------------------
__device__ __forceinline__ uint32_t smem_u32(const void* p) {
    uint32_t a;
    asm("{ .reg .u64 t; cvta.to.shared.u64 t, %1; cvt.u32.u64 %0, t; }"
        : "=r"(a) : "l"(p));
    return a;
}

__device__ __forceinline__ void mbar_init(uint32_t mbar, uint32_t count) {
    asm volatile("mbarrier.init.shared.b64 [%0], %1;" :: "r"(mbar), "r"(count) : "memory");
}

__device__ __forceinline__ void mbar_expect_tx(uint32_t mbar, uint32_t bytes) {
    asm volatile("mbarrier.arrive.expect_tx.shared.b64 _, [%0], %1;"
                 :: "r"(mbar), "r"(bytes) : "memory");
}

__device__ __forceinline__ void mbar_arrive(uint32_t mbar) {
    asm volatile("mbarrier.arrive.shared.b64 _, [%0];" :: "r"(mbar) : "memory");
}

__device__ __forceinline__ void mbar_wait(uint32_t mbar, uint32_t parity) {
    asm volatile(
        "{\n\t"
        ".reg .pred P;\n\t"
        "WLOOP_%=:\n\t"
        "mbarrier.try_wait.parity.acquire.cta.shared::cta.b64 P, [%0], %1, 0x989680;\n\t"
        "@P bra.uni WDONE_%=;\n\t"
        "bra.uni WLOOP_%=;\n\t"
        "WDONE_%=:\n\t"
        "}"
        :: "r"(mbar), "r"(parity) : "memory");
}

__device__ __forceinline__ void mbar_wait_relaxed(uint32_t mbar, uint32_t parity) {
    asm volatile(
        "{\n\t"
        ".reg .pred P;\n\t"
        "WLOOP_%=:\n\t"
        "mbarrier.try_wait.parity.relaxed.cta.shared::cta.b64 P, [%0], %1, 0x989680;\n\t"
        "@P bra.uni WDONE_%=;\n\t"
        "bra.uni WLOOP_%=;\n\t"
        "WDONE_%=:\n\t"
        "}"
        :: "r"(mbar), "r"(parity) : "memory");
}

__device__ __forceinline__ void tma_load_2d(uint32_t smem_dst, const void* map,
                                            int cx, int cy, uint32_t mbar) {
    asm volatile(
        "cp.async.bulk.tensor.2d.shared::cta.global.tile.mbarrier::complete_tx::bytes "
        "[%0], [%1, {%2, %3}], [%4];"
        :: "r"(smem_dst), "l"(map), "r"(cx), "r"(cy), "r"(mbar) : "memory");
}

__device__ __forceinline__ void ldsm_x4(uint32_t& r0, uint32_t& r1, uint32_t& r2,
                                        uint32_t& r3, uint32_t addr) {
    asm volatile("ldmatrix.sync.aligned.m8n8.x4.shared.b16 {%0,%1,%2,%3}, [%4];"
                 : "=r"(r0), "=r"(r1), "=r"(r2), "=r"(r3) : "r"(addr));
}

__device__ __forceinline__ void mma16816(float* c, const uint32_t* a, const uint32_t* b) {
    asm volatile(
        "mma.sync.aligned.m16n8k16.row.col.f32.f16.f16.f32 "
        "{%0,%1,%2,%3}, {%4,%5,%6,%7}, {%8,%9}, {%0,%1,%2,%3};"
        : "+f"(c[0]), "+f"(c[1]), "+f"(c[2]), "+f"(c[3])
        : "r"(a[0]), "r"(a[1]), "r"(a[2]), "r"(a[3]), "r"(b[0]), "r"(b[1]));
}

// banded raster: 8 consecutive m-tiles sweep n together (L2 reuse)
__device__ __forceinline__ void tile_coords(int t, int& m0, int& n0) {
    const int band = t / (NT_TILES * BAND);
    const int r = t % (NT_TILES * BAND);
    m0 = (band * BAND + (r & (BAND - 1))) * BM;
    n0 = (r / BAND) * BN;
}

// Work list. For bid < 2*NREM the FIRST item (i=0) is a K-half of a remainder
// tile (partners start in sync at launch; skew is then re-absorbed by the 37
// full tiles that follow). mode: 0=full, 1=low half (store partial),
// 2=high half (combine + store out).
__device__ __forceinline__ int num_work(int bid) {
    return NFULL + ((bid < 2 * NREM) ? 1 : 0);
}
__device__ __forceinline__ void work_item(int bid, int i, int& t, int& nkt,
                                          int& kbase, int& mode, int& slot) {
    if (bid < 2 * NREM) {
        if (i == 0) {
            if (bid < NREM) {
                t = NFULL * GRID_CTAS + bid; nkt = HKT; kbase = 0; mode = 1;
                slot = bid;
            } else {
                t = NFULL * GRID_CTAS + (bid - NREM); nkt = HKT; kbase = HKT;
                mode = 2; slot = bid - NREM;
            }
            return;
        }
        t = bid + (i - 1) * GRID_CTAS; nkt = KTILES; kbase = 0; mode = 0; slot = 0;
    } else {
        t = bid + i * GRID_CTAS; nkt = KTILES; kbase = 0; mode = 0; slot = 0;
    }
}

// ---------------------------------------------------------------------------
// Fused aux kernel (zeroes k-split flags; MLP-4 front-batched loads):
//   blocks [0, CONV_BLOCKS)           : x f32 -> f16 (4 float4 per thread)
//   blocks [CONV_BLOCKS, +DQ_BX*DQ_BY): dequant+transpose qweight -> Wt[N,K]
// ---------------------------------------------------------------------------
__global__ void __launch_bounds__(256) aux_kernel(
    const float4* __restrict__ xin, __half* __restrict__ xh,
    const int* __restrict__ qw, const float* __restrict__ sc,
    const int* __restrict__ qz, __half* __restrict__ wt) {
    __shared__ __half s[64][136];
    const int tid = threadIdx.x;

    if (blockIdx.x == 0 && tid < NREM) g_flag[tid] = 0;

    if (blockIdx.x < CONV_BLOCKS) {
        // 4 front-batched float4 loads per thread (MLP_p1 = 4)
        const size_t base = (size_t)blockIdx.x * 1024 + tid;
        float4 v[4];
#pragma unroll
        for (int j = 0; j < 4; j++) v[j] = __ldcs(&xin[base + j * 256]);
#pragma unroll
        for (int j = 0; j < 4; j++) {
            __half2 lo = __floats2half2_rn(v[j].x, v[j].y);
            __half2 hi = __floats2half2_rn(v[j].z, v[j].w);
            uint2 pack;
            pack.x = *reinterpret_cast<uint32_t*>(&lo);
            pack.y = *reinterpret_cast<uint32_t*>(&hi);
            *reinterpret_cast<uint2*>(&xh[4 * (base + j * 256)]) = pack;
        }
        return;
    }

    const int b = blockIdx.x - CONV_BLOCKS;
    const int n_local = tid & 63;
    const int r0 = tid >> 6;
    const int n0 = (b % DQ_BX) * 64;
    const int k20 = (b / DQ_BX) * 64;
    const int n = n0 + n_local;

    const int g = k20 >> 6;  // GROUP_SIZE=128 -> 64 k2-rows per group
    const float sf = sc[(size_t)g * NTOT + n];
    const int zq = qz[(size_t)(g >> 1) * NTOT + n];
    const int z = (zq >> ((g & 1) * 4)) & 15;

    // front-batch qweight loads in two groups of 8 (MLP_p1 = 8)
    int q[16];
#pragma unroll
    for (int i = 0; i < 8; i++)
        q[i] = __ldcs(&qw[(size_t)(k20 + i * 4 + r0) * NTOT + n]);
#pragma unroll
    for (int i = 0; i < 8; i++) {
        const int k2r = i * 4 + r0;
        s[n_local][2 * k2r]     = __float2half_rn((float)((q[i] & 15) - z) * sf);
        s[n_local][2 * k2r + 1] = __float2half_rn((float)(((q[i] >> 4) & 15) - z) * sf);
    }
#pragma unroll
    for (int i = 8; i < 16; i++)
        q[i] = __ldcs(&qw[(size_t)(k20 + i * 4 + r0) * NTOT + n]);
#pragma unroll
    for (int i = 8; i < 16; i++) {
        const int k2r = i * 4 + r0;
        s[n_local][2 * k2r]     = __float2half_rn((float)((q[i] & 15) - z) * sf);
        s[n_local][2 * k2r + 1] = __float2half_rn((float)(((q[i] >> 4) & 15) - z) * sf);
    }
    __syncthreads();

#pragma unroll
    for (int it = 0; it < 4; it++) {
        const int idx = it * 256 + tid;
        const int r = idx >> 4;
        const int c = idx & 15;
        uint4 v = *reinterpret_cast<const uint4*>(&s[r][c * 8]);
        *reinterpret_cast<uint4*>(
            &wt[(size_t)(n0 + r) * KTOT + 2 * k20 + c * 8]) = v;
    }
}

// ---------------------------------------------------------------------------
// Kernel 2: PERSISTENT TMA + mma.sync GEMM with K-split remainder balancing
// (split items FIRST) and software-pipelined stage boundaries. 128x128 tile,
// BK=128, 3-stage ring, fragment double-buffering, hoisted stage wait.
// IDENTICAL to the round-12 best (1408.1 us).
// ---------------------------------------------------------------------------
__global__ void __launch_bounds__(288, 1) int4gemm_kernel(
    const __grid_constant__ CUtensorMap tma_a,
    const __grid_constant__ CUtensorMap tma_b,
    float* __restrict__ out) {
    extern __shared__ __align__(1024) char smem[];
    const uint32_t sb = smem_u32(smem);
    const int tid = threadIdx.x;
    const int wid = tid >> 5;
    const int l = tid & 31;
    const int bid = blockIdx.x;
    const int nwork = num_work(bid);

    if (tid == 0) {
#pragma unroll
        for (int s = 0; s < STAGES; s++) {
            mbar_init(sb + OFF_FULL + 8 * s, 1);
            mbar_init(sb + OFF_EMPTY + 8 * s, 8);
        }
        asm volatile("fence.mbarrier_init.release.cluster;" ::: "memory");
    }
    __syncthreads();

    if (wid == 8) {
        // ---- producer: continuous TMA stream over this CTA's work list ----
        if (l == 0) {
            int s = 0, pe = 1;
            for (int i = 0; i < nwork; i++) {
                int t, nkt, kbase, mode, slot;
                work_item(bid, i, t, nkt, kbase, mode, slot);
                int m0, n0;
                tile_coords(t, m0, n0);
                for (int kt = 0; kt < nkt; kt++) {
                    const int kc = (kbase + kt) * BK;
                    mbar_wait_relaxed(sb + OFF_EMPTY + 8 * s, pe);
                    const uint32_t fb = sb + OFF_FULL + 8 * s;
                    mbar_expect_tx(fb, A_ST_BYTES + B_ST_BYTES);
                    const uint32_t aD = sb + OFF_A + s * A_ST_BYTES;
                    const uint32_t bD = sb + OFF_B + s * B_ST_BYTES;
                    tma_load_2d(aD, (const void*)&tma_a, kc, m0, fb);
                    tma_load_2d(aD + SUB_BYTES, (const void*)&tma_a, kc + 64, m0, fb);
                    tma_load_2d(bD, (const void*)&tma_b, kc, n0, fb);
                    tma_load_2d(bD + SUB_BYTES, (const void*)&tma_b, kc + 64, n0, fb);
                    if (++s == STAGES) { s = 0; pe ^= 1; }
                }
            }
        }
        return;
    }

    // ---- consumers ----
    const int wm = wid & 3;
    const int wn = wid >> 2;

    const uint32_t rowA = wm * 32 + (l & 15);
    const uint32_t xorA = (rowA & 7) << 4;
    const uint32_t colA = (l >> 4) * 16;
    const uint32_t aOff = rowA * 128;

    const uint32_t rowB = wn * 64 + (l & 7) + ((l >> 4) & 1) * 8;
    const uint32_t xorB = (l & 7) << 4;
    const uint32_t colB = ((l >> 3) & 1) * 16;
    const uint32_t bOff = rowB * 128;

    float c[2][8][4];
    uint32_t a[2][2][4];
    uint32_t b[2][8][2];

#define LOADF(buf, ksub)                                                        \
    do {                                                                        \
        const uint32_t aS = aB + ((ksub) >> 2) * SUB_BYTES;                     \
        const uint32_t bS = bB + ((ksub) >> 2) * SUB_BYTES;                     \
        const uint32_t kc = ((ksub) & 3) * 32;                                  \
        _Pragma("unroll")                                                       \
        for (int mt = 0; mt < 2; mt++)                                          \
            ldsm_x4(a[buf][mt][0], a[buf][mt][1], a[buf][mt][2], a[buf][mt][3], \
                    aS + aOff + mt * 2048 + ((kc + colA) ^ xorA));              \
        _Pragma("unroll")                                                       \
        for (int np = 0; np < 4; np++) {                                        \
            uint32_t r0, r1, r2, r3;                                            \
            ldsm_x4(r0, r1, r2, r3,                                             \
                    bS + bOff + np * 2048 + ((kc + colB) ^ xorB));              \
            b[buf][2 * np][0] = r0; b[buf][2 * np][1] = r1;                     \
            b[buf][2 * np + 1][0] = r2; b[buf][2 * np + 1][1] = r3;             \
        }                                                                       \
    } while (0)

#define MMABLK(buf)                                                             \
    do {                                                                        \
        _Pragma("unroll")                                                       \
        for (int mt = 0; mt < 2; mt++)                                          \
            _Pragma("unroll")                                                   \
            for (int nt = 0; nt < 8; nt++)                                      \
                mma16816(c[mt][nt], a[buf][mt], b[buf][nt]);                    \
    } while (0)

    int s = 0, pf = 0;
    const int rq = l >> 2;
    const int cq = (l & 3) * 2;

    for (int i = 0; i < nwork; i++) {
        int t, nkt, kbase, mode, slot;
        work_item(bid, i, t, nkt, kbase, mode, slot);
        int m0, n0;
        tile_coords(t, m0, n0);

#pragma unroll
        for (int mt = 0; mt < 2; mt++)
#pragma unroll
            for (int nt = 0; nt < 8; nt++)
#pragma unroll
                for (int j = 0; j < 4; j++) c[mt][nt][j] = 0.0f;

        mbar_wait(sb + OFF_FULL + 8 * s, pf);
        uint32_t aB = sb + OFF_A + s * A_ST_BYTES;
        uint32_t bB = sb + OFF_B + s * B_ST_BYTES;
        LOADF(0, 0);

        for (int kt = 0; kt < nkt; kt++) {
#pragma unroll
            for (int ks = 0; ks < 7; ks++) {
                LOADF((ks & 1) ^ 1, ks + 1);
                MMABLK(ks & 1);
            }
            MMABLK(1);
            if (l == 0) mbar_arrive(sb + OFF_EMPTY + 8 * s);
            if (++s == STAGES) { s = 0; pf ^= 1; }
            if (kt != nkt - 1) {
                mbar_wait(sb + OFF_FULL + 8 * s, pf);
                aB = sb + OFF_A + s * A_ST_BYTES;
                bB = sb + OFF_B + s * B_ST_BYTES;
                LOADF(0, 0);
            }
        }

        // ---- epilogue ----
        if (mode == 0) {
            const int mb = m0 + wm * 32;
            const int nb = n0 + wn * 64;
#pragma unroll
            for (int mt = 0; mt < 2; mt++) {
#pragma unroll
                for (int nt = 0; nt < 8; nt++) {
                    const size_t row = (size_t)(mb + mt * 16 + rq);
                    const size_t col = (size_t)(nb + nt * 8 + cq);
                    __stcs(reinterpret_cast<float2*>(&out[row * NTOT + col]),
                           make_float2(c[mt][nt][0], c[mt][nt][1]));
                    __stcs(reinterpret_cast<float2*>(&out[(row + 8) * NTOT + col]),
                           make_float2(c[mt][nt][2], c[mt][nt][3]));
                }
            }
        } else if (mode == 1) {
            float* scr = g_part + (size_t)slot * (BM * BN);
#pragma unroll
            for (int mt = 0; mt < 2; mt++) {
#pragma unroll
                for (int nt = 0; nt < 8; nt++) {
                    const int row = wm * 32 + mt * 16 + rq;
                    const int col = wn * 64 + nt * 8 + cq;
                    *reinterpret_cast<float2*>(&scr[row * BN + col]) =
                        make_float2(c[mt][nt][0], c[mt][nt][1]);
                    *reinterpret_cast<float2*>(&scr[(row + 8) * BN + col]) =
                        make_float2(c[mt][nt][2], c[mt][nt][3]);
                }
            }
            asm volatile("bar.sync 1, 256;" ::: "memory");
            if (tid == 0) {
                __threadfence();
                atomicExch(&g_flag[slot], 1);
            }
        } else {
            if (tid == 0) {
                while (atomicAdd(&g_flag[slot], 0) == 0) {}
                __threadfence();
            }
            asm volatile("bar.sync 1, 256;" ::: "memory");
            const float* scr = g_part + (size_t)slot * (BM * BN);
            const int mb = m0 + wm * 32;
            const int nb = n0 + wn * 64;
#pragma unroll
            for (int mt = 0; mt < 2; mt++) {
#pragma unroll
                for (int nt = 0; nt < 8; nt++) {
                    const int row = wm * 32 + mt * 16 + rq;
                    const int col = wn * 64 + nt * 8 + cq;
                    float2 p0 = *reinterpret_cast<const float2*>(&scr[row * BN + col]);
                    float2 p1 = *reinterpret_cast<const float2*>(&scr[(row + 8) * BN + col]);
                    const size_t grow = (size_t)(mb + mt * 16 + rq);
                    const size_t gcol = (size_t)(nb + nt * 8 + cq);
                    __stcs(reinterpret_cast<float2*>(&out[grow * NTOT + gcol]),
                           make_float2(c[mt][nt][0] + p0.x, c[mt][nt][1] + p0.y));
                    __stcs(reinterpret_cast<float2*>(&out[(grow + 8) * NTOT + gcol]),
                           make_float2(c[mt][nt][2] + p1.x, c[mt][nt][3] + p1.y));
                }
            }
        }
    }
#undef LOADF
#undef MMABLK
}

// ---------------------------------------------------------------------------
// host side
// ---------------------------------------------------------------------------
typedef CUresult (*PFN_encodeTiled)(
    CUtensorMap*, CUtensorMapDataType, cuuint32_t, void*,
    const cuuint64_t*, const cuuint64_t*, const cuuint32_t*, const cuuint32_t*,
    CUtensorMapInterleave, CUtensorMapSwizzle, CUtensorMapL2promotion,
    CUtensorMapFloatOOBfill);

static void encode_2d_f16(PFN_encodeTiled enc, CUtensorMap* m, void* ptr,
                          uint64_t d0, uint64_t d1, uint32_t b0, uint32_t b1) {
    cuuint64_t dims[2] = {d0, d1};
    cuuint64_t strides[1] = {d0 * 2};
    cuuint32_t box[2] = {b0, b1};
    cuuint32_t es[2] = {1, 1};
    enc(m, CU_TENSOR_MAP_DATA_TYPE_FLOAT16, 2, ptr, dims, strides, box, es,
        CU_TENSOR_MAP_INTERLEAVE_NONE, CU_TENSOR_MAP_SWIZZLE_128B,
        CU_TENSOR_MAP_L2_PROMOTION_L2_128B, CU_TENSOR_MAP_FLOAT_OOB_FILL_NONE);
}

extern "C" void kernel_launch(void* const* d_in, const int* in_sizes, int n_in,
                              void* d_out, int out_size) {
    const float* x = (const float*)d_in[0];
    const int* qw = (const int*)d_in[1];
    const float* sc = (const float*)d_in[2];
    const int* qz = (const int*)d_in[3];
    float* out = (float*)d_out;

    void* wt = nullptr;
    cudaGetSymbolAddress(&wt, g_Wt);
    void* xh = nullptr;
    cudaGetSymbolAddress(&xh, g_xh);

    // 0+1) fused: x f32->f16 convert AND dequant+transpose (+ flag reset)
    aux_kernel<<<CONV_BLOCKS + DQ_BX * DQ_BY, 256>>>(
        (const float4*)x, (__half*)xh, qw, sc, qz, (__half*)wt);

    // 2) tensor maps (box 64 cols = 128B = SW128 atom)
    PFN_encodeTiled enc = nullptr;
    cudaDriverEntryPointQueryResult qr;
    cudaGetDriverEntryPointByVersion("cuTensorMapEncodeTiled", (void**)&enc,
                                     12000, cudaEnableDefault, &qr);

    CUtensorMap map_a, map_b;
    encode_2d_f16(enc, &map_a, xh, KTOT, MTOT, 64, BM);   // xh[M,K] f16
    encode_2d_f16(enc, &map_b, wt, KTOT, NTOT, 64, BN);   // Wt[N,K] f16

    cudaFuncSetAttribute(int4gemm_kernel,
                         cudaFuncAttributeMaxDynamicSharedMemorySize, SMEM_TOTAL);

    int4gemm_kernel<<<GRID_CTAS, 288, SMEM_TOTAL>>>(map_a, map_b, out);
}